// round 17
// baseline (speedup 1.0000x reference)
#include <cuda_runtime.h>
#include <math_constants.h>

#define BB     8
#define NN     4096
#define BNN    (BB * NN)
#define CIN    128
#define EOUT   5
#define SEMOUT 13
#define KSEL   30
#define TP     32
#define XPAD   36
#define NSLICE 2
#define SLEN   (NN / NSLICE)
#define KQT    128
#define CHUNK  256

#define FINF  __int_as_float(0x7f800000)
#define FNINF __int_as_float(0xff800000)

// ---------------- scratch (static __device__, no runtime alloc) ----------------
__device__ float  g_fsemT[BNN * CIN];            // 16MB [b][n][c]
__device__ float  g_WT[CIN * CIN];               // W_adapt^T: [cin][cout]
__device__ float4 g_tA[BNN];                     // (e0,e1,e2,e3)
__device__ float2 g_tB[BNN];                     // (e4, r/2)  [r = ||e||^2]
__device__ float  g_pd[BNN * NSLICE * KSEL];     // partial half-dists (r/2 - dot)
__device__ int    g_pi[BNN * NSLICE * KSEL];     // partial indices

// ================================================================
// Phase 0: transpose W_adapt once (64KB, stays L2-resident)
// ================================================================
__global__ void wt_kernel(const float* __restrict__ W_adapt)
{
    const int i = blockIdx.x * 256 + threadIdx.x;   // i = c*128 + o
    const int c = i >> 7, o = i & 127;
    g_WT[i] = W_adapt[o * 128 + c];
}

// ================================================================
// Phase 1 — R13 verbatim except g_tB stores (e4, r/2)
// ================================================================
__global__ void __launch_bounds__(128, 6) phase1_kernel(
    const float* __restrict__ f_sem, const float* __restrict__ f_ins,
    const float* __restrict__ b_adapt,
    const float* __restrict__ gamma, const float* __restrict__ beta,
    const float* __restrict__ W_ins, const float* __restrict__ b_ins,
    float* __restrict__ e_out)
{
    extern __shared__ float sm1[];
    float* Xs = sm1;                      // 128*36 (reused as Ys)
    float* Wi = Xs + 128 * XPAD;          // 5*128 + 8

    const int tid = threadIdx.x;
    const int blk = blockIdx.x;
    const int b   = blk >> 7;
    const int n0  = (blk & 127) * TP;

    for (int i = tid; i < EOUT * 128; i += 128) Wi[i] = W_ins[i];
    if (tid < EOUT) Wi[EOUT * 128 + tid] = b_ins[tid];

    const float* fs = f_sem + ((size_t)b * CIN) * NN + n0;
    for (int i = tid; i < 128 * TP; i += 128) {
        int c = i >> 5, p = i & 31;
        Xs[c * XPAD + p] = fs[(size_t)c * NN + p];
    }
    __syncthreads();

    {
        float* dst = g_fsemT + ((size_t)(b * NN + n0)) * CIN + tid;
        #pragma unroll 4
        for (int p = 0; p < TP; p++)
            dst[(size_t)p * CIN] = Xs[tid * XPAD + p];
    }

    float acc[TP];
    #pragma unroll
    for (int p = 0; p < TP; p++) acc[p] = 0.f;

    const float* wt = g_WT + tid;
    #pragma unroll 4
    for (int c = 0; c < CIN; c++) {
        float w = __ldg(wt + c * CIN);
        const float4* xr = (const float4*)(Xs + c * XPAD);
        #pragma unroll
        for (int p4 = 0; p4 < TP / 4; p4++) {
            float4 x = xr[p4];
            acc[4 * p4 + 0] = fmaf(w, x.x, acc[4 * p4 + 0]);
            acc[4 * p4 + 1] = fmaf(w, x.y, acc[4 * p4 + 1]);
            acc[4 * p4 + 2] = fmaf(w, x.z, acc[4 * p4 + 2]);
            acc[4 * p4 + 3] = fmaf(w, x.w, acc[4 * p4 + 3]);
        }
    }

    const float g  = gamma[tid];
    const float bb = fmaf(g, b_adapt[tid], beta[tid]);
    const float* fi = f_ins + ((size_t)(b * CIN + tid)) * NN + n0;
    float y[TP];
    #pragma unroll
    for (int p = 0; p < TP; p++) {
        float a = fmaxf(fmaf(g, acc[p], bb), 0.f);
        y[p] = fi[p] + a;
    }
    __syncthreads();
    #pragma unroll
    for (int p = 0; p < TP; p++) Xs[tid * XPAD + p] = y[p];
    __syncthreads();

    if (tid < TP) {
        const int p = tid;
        float e[EOUT];
        #pragma unroll
        for (int j = 0; j < EOUT; j++) e[j] = Wi[EOUT * 128 + j];
        #pragma unroll 4
        for (int c = 0; c < 128; c++) {
            float x = Xs[c * XPAD + p];
            #pragma unroll
            for (int j = 0; j < EOUT; j++) e[j] = fmaf(Wi[j * 128 + c], x, e[j]);
        }
        float r = 0.f;
        #pragma unroll
        for (int j = 0; j < EOUT; j++) r = fmaf(e[j], e[j], r);
        const int n = n0 + p;
        float* eo = e_out + (size_t)b * EOUT * NN + n;
        #pragma unroll
        for (int j = 0; j < EOUT; j++) eo[(size_t)j * NN] = e[j];
        g_tA[b * NN + n] = make_float4(e[0], e[1], e[2], e[3]);
        g_tB[b * NN + n] = make_float2(e[4], 0.5f * r);
    }
}

// ================================================================
// Phase 2a: register-resident windows, no accept queue.
// score s = r/2 - dot (5 FMA from negated query); keep 30 smallest.
// smem 36KB -> 6 blocks/SM.
// ================================================================
#define INSERT_KEPT(v, id) do {                                   \
    myhd[amax * KQT] = (v);                                       \
    myhi[amax * KQT] = (id);                                      \
    float _bm = myhd[0]; int _ba = 0;                             \
    _Pragma("unroll")                                             \
    for (int _t = 1; _t < KSEL; _t++) {                           \
        float _hv = myhd[_t * KQT];                               \
        bool _g = _hv > _bm;                                      \
        _bm = _g ? _hv : _bm;                                     \
        _ba = _g ? _t : _ba;                                      \
    }                                                             \
    tau = _bm; amax = _ba;                                        \
} while (0)

__global__ void __launch_bounds__(KQT, 6) knn_partial_kernel()
{
    extern __shared__ float smk[];
    float4* st4 = (float4*)smk;                    // CHUNK * 16B
    float2* st2 = (float2*)(st4 + CHUNK);          // CHUNK * 8B
    float*  hd  = (float*)(st2 + CHUNK);           // KSEL*KQT (unordered kept)
    int*    hi  = (int*)(hd + KSEL * KQT);         // KSEL*KQT

    const int tid  = threadIdx.x;
    const int b    = blockIdx.x >> 6;              // 64 blocks per batch
    const int qblk = (blockIdx.x >> 1) & 31;
    const int sl   = blockIdx.x & 1;
    const int q    = (qblk << 7) + tid;
    const int base = sl * SLEN;

    const float4* tA4 = g_tA + b * NN;
    const float2* tB2 = g_tB + b * NN;

    const float4 Qt = __ldg(&tA4[q]);
    const float4 nQ = make_float4(-Qt.x, -Qt.y, -Qt.z, -Qt.w);
    const float  nq4 = -__ldg(&tB2[q]).x;

    float* myhd = hd + tid; int* myhi = hi + tid;

    // stage chunk 0
    st4[tid]       = __ldg(&tA4[base + tid]);
    st2[tid]       = __ldg(&tB2[base + tid]);
    st4[tid + 128] = __ldg(&tA4[base + tid + 128]);
    st2[tid + 128] = __ldg(&tB2[base + tid + 128]);
    __syncthreads();

    // prefill 30 slots (unordered), then one rescan for tau/amax
    #pragma unroll
    for (int j = 0; j < KSEL; j++) {
        float4 ta = st4[j];
        float2 tb = st2[j];
        float d = tb.y;
        d = fmaf(ta.x, nQ.x, d);
        d = fmaf(ta.y, nQ.y, d);
        d = fmaf(ta.z, nQ.z, d);
        d = fmaf(ta.w, nQ.w, d);
        d = fmaf(tb.x, nq4, d);
        myhd[j * KQT] = d;
        myhi[j * KQT] = base + j;
    }
    float tau; int amax;
    {
        float bm = myhd[0]; int ba = 0;
        #pragma unroll
        for (int t = 1; t < KSEL; t++) {
            float hv = myhd[t * KQT];
            bool g = hv > bm;
            bm = g ? hv : bm;
            ba = g ? t : ba;
        }
        tau = bm; amax = ba;
    }

    #pragma unroll 1
    for (int ch = 0; ch < SLEN / CHUNK; ch++) {
        if (ch) {
            __syncthreads();
            const int mg = base + ch * CHUNK;
            st4[tid]       = __ldg(&tA4[mg + tid]);
            st2[tid]       = __ldg(&tB2[mg + tid]);
            st4[tid + 128] = __ldg(&tA4[mg + tid + 128]);
            st2[tid + 128] = __ldg(&tB2[mg + tid + 128]);
            __syncthreads();
        }
        const int mgc = base + ch * CHUNK;
        int k = 0;

        if (ch == 0) {
            // candidates 30, 31 (scalar), then aligned windows from 32
            for (k = KSEL; k < 32; k++) {
                float4 ta = st4[k];
                float2 tb = st2[k];
                float d = tb.y;
                d = fmaf(ta.x, nQ.x, d);
                d = fmaf(ta.y, nQ.y, d);
                d = fmaf(ta.z, nQ.z, d);
                d = fmaf(ta.w, nQ.w, d);
                d = fmaf(tb.x, nq4, d);
                if (d < tau) INSERT_KEPT(d, mgc + k);
            }
        }

        #pragma unroll 1
        for (; k < CHUNK; k += 8) {
            float sc[8];
            float mn = FINF;
            #pragma unroll
            for (int j = 0; j < 8; j++) {
                float4 ta = st4[k + j];
                float2 tb = st2[k + j];
                float d = tb.y;
                d = fmaf(ta.x, nQ.x, d);
                d = fmaf(ta.y, nQ.y, d);
                d = fmaf(ta.z, nQ.z, d);
                d = fmaf(ta.w, nQ.w, d);
                d = fmaf(tb.x, nq4, d);
                sc[j] = d;
                mn = fminf(mn, d);
            }
            if (__any_sync(0xffffffffu, mn < tau)) {
                #pragma unroll
                for (int j = 0; j < 8; j++) {
                    if (sc[j] < tau) INSERT_KEPT(sc[j], mgc + k + j);
                }
            }
        }
    }

    const size_t off = ((size_t)(b * NN + q) * NSLICE + sl) * KSEL;
    #pragma unroll
    for (int j = 0; j < KSEL; j++) {
        g_pd[off + j] = myhd[j * KQT];
        g_pi[off + j] = myhi[j * KQT];
    }
}

// ================================================================
// Phase 3: fused merge + gather (R13 verbatim)
// ================================================================
__global__ void __launch_bounds__(256) gather_kernel(
    const float* __restrict__ W_sem, const float* __restrict__ b_sem,
    float* __restrict__ p_out)
{
    __shared__ int sel[8][32];

    const int w    = threadIdx.x >> 5;
    const int warp = (blockIdx.x << 3) + w;
    const int lane = threadIdx.x & 31;
    const int b = warp >> 12, n = warp & (NN - 1);

    const size_t off = (size_t)warp * (NSLICE * KSEL);
    float s0 = FINF, s1 = FINF;
    int   i0 = 0x7fffffff, i1 = 0x7fffffff;
    if (lane < KSEL) {
        s0 = g_pd[off + lane];         i0 = g_pi[off + lane];
        s1 = g_pd[off + KSEL + lane];  i1 = g_pi[off + KSEL + lane];
    }

    int r0 = 0, r1 = 0;
    #pragma unroll
    for (int j = 0; j < KSEL; j++) {
        float a  = __shfl_sync(0xffffffffu, s0, j);
        int   ai = __shfl_sync(0xffffffffu, i0, j);
        r0 += (a < s0) || (a == s0 && ai < i0);
        r1 += (a < s1) || (a == s1 && ai < i1);
        float c  = __shfl_sync(0xffffffffu, s1, j);
        int   ci = __shfl_sync(0xffffffffu, i1, j);
        r0 += (c < s0) || (c == s0 && ci < i0);
        r1 += (c < s1) || (c == s1 && ci < i1);
    }
    if (lane < KSEL) {
        if (r0 < KSEL) sel[w][r0] = i0;
        if (r1 < KSEL) sel[w][r1] = i1;
    }
    __syncwarp();

    int myid = sel[w][lane < KSEL ? lane : 0];

    const float* base = g_fsemT + ((size_t)b * NN) * CIN + (lane << 2);
    float4 vmax = make_float4(FNINF, FNINF, FNINF, FNINF);
    #pragma unroll 6
    for (int k = 0; k < KSEL; k++) {
        int j = __shfl_sync(0xffffffffu, myid, k);
        float4 v = *(const float4*)(base + (size_t)j * CIN);
        vmax.x = fmaxf(vmax.x, v.x);
        vmax.y = fmaxf(vmax.y, v.y);
        vmax.z = fmaxf(vmax.z, v.z);
        vmax.w = fmaxf(vmax.w, v.w);
    }

    float out[SEMOUT];
    #pragma unroll
    for (int o = 0; o < SEMOUT; o++) {
        float4 wv = *(const float4*)(W_sem + o * CIN + (lane << 2));
        float a = wv.x * vmax.x;
        a = fmaf(wv.y, vmax.y, a);
        a = fmaf(wv.z, vmax.z, a);
        a = fmaf(wv.w, vmax.w, a);
        a += __shfl_xor_sync(0xffffffffu, a, 16);
        a += __shfl_xor_sync(0xffffffffu, a, 8);
        a += __shfl_xor_sync(0xffffffffu, a, 4);
        a += __shfl_xor_sync(0xffffffffu, a, 2);
        a += __shfl_xor_sync(0xffffffffu, a, 1);
        out[o] = a;
    }
    if (lane == 0) {
        float* dst = p_out + ((size_t)b * SEMOUT) * NN + n;
        #pragma unroll
        for (int o = 0; o < SEMOUT; o++)
            dst[(size_t)o * NN] = out[o] + b_sem[o];
    }
}

// ================================================================
extern "C" void kernel_launch(void* const* d_in, const int* in_sizes, int n_in,
                              void* d_out, int out_size)
{
    (void)in_sizes; (void)n_in; (void)out_size;
    const float* f_sem   = (const float*)d_in[0];
    const float* f_ins   = (const float*)d_in[1];
    const float* W_adapt = (const float*)d_in[2];
    const float* b_adapt = (const float*)d_in[3];
    const float* gamma   = (const float*)d_in[4];
    const float* beta    = (const float*)d_in[5];
    const float* W_ins   = (const float*)d_in[6];
    const float* b_ins   = (const float*)d_in[7];
    const float* W_sem   = (const float*)d_in[8];
    const float* b_sem   = (const float*)d_in[9];

    float* p_out = (float*)d_out;                       // [B,13,N]
    float* e_out = p_out + (size_t)BB * SEMOUT * NN;    // [B,5,N]

    const int smem1 = (128 * XPAD + EOUT * 128 + 8) * 4;        // ~21KB
    const int smem2 = CHUNK * 24 + KSEL * KQT * 8;              // 36KB

    cudaFuncSetAttribute(phase1_kernel,      cudaFuncAttributeMaxDynamicSharedMemorySize, smem1);
    cudaFuncSetAttribute(knn_partial_kernel, cudaFuncAttributeMaxDynamicSharedMemorySize, smem2);

    wt_kernel<<<CIN * CIN / 256, 256>>>(W_adapt);
    phase1_kernel<<<BB * (NN / TP), 128, smem1>>>(
        f_sem, f_ins, b_adapt, gamma, beta, W_ins, b_ins, e_out);
    knn_partial_kernel<<<BB * (NN / KQT) * NSLICE, KQT, smem2>>>();
    gather_kernel<<<BNN / 8, 256>>>(W_sem, b_sem, p_out);
}